// round 5
// baseline (speedup 1.0000x reference)
#include <cuda_runtime.h>
#include <math.h>

#define HH 512
#define WW 512
#define CC 64
#define HW (HH*WW)
#define TILE_W 32
#define TILE_H 16
#define HALO 2
#define SXW (TILE_W + 2*HALO)   // 36
#define SXH (TILE_H + 2*HALO)   // 20
#define SXP 38                  // padded, even row stride
#define CI_CHUNK 8
#define CO_BLK 16
#define SX_FLOATS (CI_CHUNK * SXH * SXP)          // 6080
#define SX_BYTES  (SX_FLOATS * 4)                 // 24320
#define SW2_ELEMS (CI_CHUNK * 9 * CO_BLK)         // 1152 ull
#define SMEM_BYTES (SX_BYTES + SW2_ELEMS * 8)     // 33536

typedef unsigned long long ull;

__device__ float g_xori[CC * HW];
__device__ unsigned char g_md[HW];

__device__ __forceinline__ int reflect512(int i) {
    i = abs(i);
    return min(i, 1022 - i);
}

__device__ __forceinline__ float gelu_exact(float v) {
    return 0.5f * v * (1.0f + erff(v * 0.70710678118654752f));
}

__device__ __forceinline__ ull splat2(float x) {
    ull r;
    asm("mov.b64 %0, {%1, %1};" : "=l"(r) : "f"(x));
    return r;
}
__device__ __forceinline__ void ffma2(ull& a, ull x, ull w) {
    asm("fma.rn.f32x2 %0, %1, %2, %0;" : "+l"(a) : "l"(x), "l"(w));
}
__device__ __forceinline__ float2 unpack2(ull a) {
    float2 f;
    asm("mov.b64 {%0, %1}, %2;" : "=f"(f.x), "=f"(f.y) : "l"(a));
    return f;
}

// ---------------------------------------------------------------------------
__global__ void md_kernel(const float* __restrict__ mask) {
    int x = blockIdx.x * 32 + threadIdx.x;
    int y = blockIdx.y * 8 + threadIdx.y;
    float m = 0.0f;
    #pragma unroll
    for (int dy = -2; dy <= 2; dy++) {
        int yy = y + dy;
        if (yy < 0 || yy >= HH) continue;
        #pragma unroll
        for (int dx = -2; dx <= 2; dx++) {
            int xx = x + dx;
            if (xx < 0 || xx >= WW) continue;
            m = fmaxf(m, mask[yy * WW + xx]);
        }
    }
    g_md[y * WW + x] = (m > 0.5f) ? 1 : 0;
}

// ---------------------------------------------------------------------------
// MODE 1: in = x       -> g_xori = md ? gelu(conv+b1) : x
// MODE 2: in = g_xori  -> d_out[sd] = gelu(conv+b2) + x
// 32x16 tile, 2 adjacent px/thread packed f32x2, 16 co/block.
// 3 CTAs/SM (24 warps) for latency hiding; bias pre-loaded into accs.
// ---------------------------------------------------------------------------
template <int MODE>
__global__ void __launch_bounds__(256, 3) conv_kernel(
    const float* __restrict__ xres,
    const float* __restrict__ wgt,    // (64,64,3,3) OIHW
    const float* __restrict__ bias,
    const float* __restrict__ mask,
    float* __restrict__ out)
{
    extern __shared__ __align__(16) char dsm[];
    float (*sx)[SXH][SXP] = reinterpret_cast<float(*)[SXH][SXP]>(dsm);
    ull* sw2 = reinterpret_cast<ull*>(dsm + SX_BYTES);

    const float* in = (MODE == 1) ? xres : (const float*)g_xori;

    const int tid = threadIdx.x;
    const int lx = tid & 15;         // cols 2lx, 2lx+1
    const int ly = tid >> 4;         // rows 0..15
    const int bx = blockIdx.x * TILE_W;
    const int by = blockIdx.y * TILE_H;
    const int co0 = blockIdx.z * CO_BLK;

    const int warp = tid >> 5;
    const int lane = tid & 31;
    const bool col_interior = (bx != 0) && (bx != WW - TILE_W);
    const int gxa = reflect512(bx - 2 + lane);
    const int gxb = reflect512(bx - 2 + lane + 32);

    // accumulators start at bias (splatted)
    ull acc[CO_BLK];
    #pragma unroll
    for (int j = 0; j < CO_BLK; j++) acc[j] = splat2(__ldg(&bias[co0 + j]));

    for (int cc = 0; cc < CC; cc += CI_CHUNK) {
        // --- stage input plane: one warp per ci, SXH=20 rows x SXW=36 cols ---
        {
            const float* src = in + (cc + warp) * HW;
            if (col_interior) {
                if (lane < 18) {
                    #pragma unroll 5
                    for (int r = 0; r < SXH; r++) {
                        const float* rowp = src + reflect512(by - 2 + r) * WW + (bx - 2);
                        float2 v = *reinterpret_cast<const float2*>(rowp + 2 * lane);
                        *reinterpret_cast<float2*>(&sx[warp][r][2 * lane]) = v;
                    }
                }
            } else {
                #pragma unroll 5
                for (int r = 0; r < SXH; r++) {
                    const float* rowp = src + reflect512(by - 2 + r) * WW;
                    sx[warp][r][lane] = rowp[gxa];
                    if (lane < SXW - 32) sx[warp][r][lane + 32] = rowp[gxb];
                }
            }
        }
        // --- stage weights, pre-splatted {w,w} ---
        for (int idx = tid; idx < SW2_ELEMS; idx += 256) {
            int co   = idx & 15;
            int rest = idx >> 4;      // ci*9 + k
            int ci   = rest / 9;
            int k    = rest - ci * 9;
            sw2[idx] = splat2(wgt[(co0 + co) * (CC * 9) + (cc + ci) * 9 + k]);
        }
        __syncthreads();

        #pragma unroll
        for (int ci = 0; ci < CI_CHUNK; ci++) {
            #pragma unroll
            for (int k = 0; k < 9; k++) {
                const int dy = (k / 3) * 2;
                const int dx = (k % 3) * 2;
                ull xa = *reinterpret_cast<const ull*>(&sx[ci][ly + dy][2 * lx + dx]);
                const ulonglong2* wp =
                    reinterpret_cast<const ulonglong2*>(&sw2[(ci * 9 + k) * CO_BLK]);
                #pragma unroll
                for (int j = 0; j < 8; j++) {
                    ulonglong2 w = wp[j];
                    ffma2(acc[2 * j],     xa, w.x);
                    ffma2(acc[2 * j + 1], xa, w.y);
                }
            }
        }
        __syncthreads();
    }

    // --- epilogue: 2 adjacent cols packed x 16 co ---
    const int cx = bx + 2 * lx;
    const int gy = by + ly;
    const int p = gy * WW + cx;

    if (MODE == 1) {
        const bool m0 = (g_md[p] != 0);
        const bool m1 = (g_md[p + 1] != 0);
        #pragma unroll
        for (int j = 0; j < CO_BLK; j++) {
            float2 v = unpack2(acc[j]);
            const int o = (co0 + j) * HW + p;
            float2 xr = *reinterpret_cast<const float2*>(&xres[o]);
            float2 w;
            w.x = m0 ? gelu_exact(v.x) : xr.x;
            w.y = m1 ? gelu_exact(v.y) : xr.y;
            *reinterpret_cast<float2*>(&g_xori[o]) = w;
        }
    } else {
        const bool s0 = mask[p] > 0.5f;
        const bool s1 = mask[p + 1] > 0.5f;
        if (s0 || s1) {
            #pragma unroll
            for (int j = 0; j < CO_BLK; j++) {
                float2 v = unpack2(acc[j]);
                const int o = (co0 + j) * HW + p;
                if (s0 && s1) {
                    float2 xr = *reinterpret_cast<const float2*>(&xres[o]);
                    float2 w;
                    w.x = gelu_exact(v.x) + xr.x;
                    w.y = gelu_exact(v.y) + xr.y;
                    *reinterpret_cast<float2*>(&out[o]) = w;
                } else if (s0) {
                    out[o] = gelu_exact(v.x) + xres[o];
                } else {
                    out[o + 1] = gelu_exact(v.y) + xres[o + 1];
                }
            }
        }
    }
}

// ---------------------------------------------------------------------------
__global__ void dw_kernel(
    const float* __restrict__ x,
    const float* __restrict__ w3,
    const float* __restrict__ b3,
    const float* __restrict__ mask,
    float* __restrict__ out)
{
    int gx = blockIdx.x * 256 + threadIdx.x;
    int gy = blockIdx.y;
    int c  = blockIdx.z;
    int p  = gy * WW + gx;
    if (mask[p] > 0.5f) return;

    const float* wc = w3 + c * 9;
    const float* xc = x + c * HW;
    float a = 0.0f;
    #pragma unroll
    for (int k = 0; k < 9; k++) {
        int yy = reflect512(gy + (k / 3) * 2 - 2);
        int xx = reflect512(gx + (k % 3) * 2 - 2);
        a = fmaf(xc[yy * WW + xx], wc[k], a);
    }
    out[c * HW + p] = gelu_exact(a + b3[c]) + xc[p];
}

// ---------------------------------------------------------------------------
extern "C" void kernel_launch(void* const* d_in, const int* in_sizes, int n_in,
                              void* d_out, int out_size) {
    const float* x    = (const float*)d_in[0];
    const float* mask = (const float*)d_in[1];
    const float* w1   = (const float*)d_in[2];
    const float* b1   = (const float*)d_in[3];
    const float* w2   = (const float*)d_in[4];
    const float* b2   = (const float*)d_in[5];
    const float* w3   = (const float*)d_in[6];
    const float* b3   = (const float*)d_in[7];
    float* out = (float*)d_out;

    static bool attr_set = false;
    if (!attr_set) {
        cudaFuncSetAttribute(conv_kernel<1>,
            cudaFuncAttributeMaxDynamicSharedMemorySize, SMEM_BYTES);
        cudaFuncSetAttribute(conv_kernel<2>,
            cudaFuncAttributeMaxDynamicSharedMemorySize, SMEM_BYTES);
        attr_set = true;
    }

    md_kernel<<<dim3(WW / 32, HH / 8), dim3(32, 8)>>>(mask);

    dim3 cgrid(WW / TILE_W, HH / TILE_H, CC / CO_BLK);   // 16 x 32 x 4
    conv_kernel<1><<<cgrid, 256, SMEM_BYTES>>>(x, w1, b1, mask, out);

    dw_kernel<<<dim3(WW / 256, HH, CC), 256>>>(x, w3, b3, mask, out);

    conv_kernel<2><<<cgrid, 256, SMEM_BYTES>>>(x, w2, b2, mask, out);
}

// round 7
// speedup vs baseline: 2.8427x; 2.8427x over previous
#include <cuda_runtime.h>
#include <cuda_bf16.h>
#include <math.h>
#include <stdint.h>

#define HH 512
#define WW 512
#define CC 64
#define HW (HH*WW)
#define PW 516                 // padded H/W (reflect pad 2 materialized)
#define MPX 128                // pixels per CTA tile

// smem layout (bytes)
#define ASTRIDE 144            // 64 ci * 2B = 128B payload, padded to 144 (ldmatrix conflict-free)
#define SM_AH   0
#define SM_AL   (SM_AH + 132 * ASTRIDE)        // 19008
#define SM_BH   (SM_AL + 132 * ASTRIDE)        // 38016
#define SM_BL   (SM_BH + 64 * ASTRIDE)         // 47232
#define SM_TOTAL (SM_BL + 64 * ASTRIDE)        // 56448
#define EPI_STRIDE 65                          // floats; epi buffer aliases A region

typedef unsigned short ushort_t;

// ------------------------- device globals (no allocation) -------------------
__device__ __nv_bfloat16 g_xh[(size_t)PW * PW * CC];
__device__ __nv_bfloat16 g_xl[(size_t)PW * PW * CC];
__device__ __nv_bfloat16 g_oh[(size_t)PW * PW * CC];
__device__ __nv_bfloat16 g_ol[(size_t)PW * PW * CC];
__device__ ushort_t g_w[2 * 9 * 2 * 4096];     // [conv][tap][half][ci*64+co]
__device__ unsigned char g_md_[HW];

// ------------------------- helpers ------------------------------------------
__device__ __forceinline__ int reflect512(int i) {
    i = abs(i);
    return min(i, 1022 - i);
}
__device__ __forceinline__ float gelu_exact(float v) {
    return 0.5f * v * (1.0f + erff(v * 0.70710678118654752f));
}
__device__ __forceinline__ uint32_t smem_u32(const void* p) {
    uint32_t a;
    asm("{ .reg .u64 t; cvta.to.shared.u64 t, %1; cvt.u32.u64 %0, t; }" : "=r"(a) : "l"(p));
    return a;
}
__device__ __forceinline__ void ldsm4(uint32_t (&r)[4], uint32_t addr) {
    asm volatile("ldmatrix.sync.aligned.m8n8.x4.shared.b16 {%0,%1,%2,%3}, [%4];"
                 : "=r"(r[0]), "=r"(r[1]), "=r"(r[2]), "=r"(r[3]) : "r"(addr));
}
__device__ __forceinline__ void ldsm4t(uint32_t (&r)[4], uint32_t addr) {
    asm volatile("ldmatrix.sync.aligned.m8n8.x4.trans.shared.b16 {%0,%1,%2,%3}, [%4];"
                 : "=r"(r[0]), "=r"(r[1]), "=r"(r[2]), "=r"(r[3]) : "r"(addr));
}
__device__ __forceinline__ void mma16816(float (&d)[4], const uint32_t (&a)[4],
                                         uint32_t b0, uint32_t b1) {
    asm volatile(
        "mma.sync.aligned.m16n8k16.row.col.f32.bf16.bf16.f32 "
        "{%0,%1,%2,%3}, {%4,%5,%6,%7}, {%8,%9}, {%0,%1,%2,%3};"
        : "+f"(d[0]), "+f"(d[1]), "+f"(d[2]), "+f"(d[3])
        : "r"(a[0]), "r"(a[1]), "r"(a[2]), "r"(a[3]), "r"(b0), "r"(b1));
}

// ------------------------- prepasses -----------------------------------------
__global__ void md_kernel(const float* __restrict__ mask) {
    int x = blockIdx.x * 32 + threadIdx.x;
    int y = blockIdx.y * 8 + threadIdx.y;
    float m = 0.0f;
    #pragma unroll
    for (int dy = -2; dy <= 2; dy++) {
        int yy = y + dy;
        if (yy < 0 || yy >= HH) continue;
        #pragma unroll
        for (int dx = -2; dx <= 2; dx++) {
            int xx = x + dx;
            if (xx < 0 || xx >= WW) continue;
            m = fmaxf(m, mask[yy * WW + xx]);
        }
    }
    g_md_[y * WW + x] = (m > 0.5f) ? 1 : 0;
}

// x (NCHW fp32) -> padded NHWC bf16 hi/lo
__global__ void prep_x(const float* __restrict__ x) {
    __shared__ ushort_t sh[32][66];
    __shared__ ushort_t sl[32][66];
    const int yp  = blockIdx.y;
    const int xp0 = blockIdx.x * 32;
    const int tid = threadIdx.x;
    const int warp = tid >> 5, lane = tid & 31;
    const int ry = reflect512(yp - 2);
    const int xp = xp0 + lane;
    const int rx = reflect512((xp < PW ? xp : PW - 1) - 2);
    #pragma unroll
    for (int q = 0; q < 8; q++) {
        int ci = warp * 8 + q;
        float v = x[(size_t)ci * HW + (size_t)ry * WW + rx];
        __nv_bfloat16 h = __float2bfloat16(v);
        __nv_bfloat16 l = __float2bfloat16(v - __bfloat162float(h));
        sh[lane][ci] = __bfloat16_as_ushort(h);
        sl[lane][ci] = __bfloat16_as_ushort(l);
    }
    __syncthreads();
    const int jj = tid >> 3, c0 = (tid & 7) * 8;
    const int xpw = xp0 + jj;
    if (xpw < PW) {
        size_t base = ((size_t)yp * PW + xpw) * 64 + c0;
        uint32_t a[4], b[4];
        #pragma unroll
        for (int i = 0; i < 4; i++) {
            a[i] = (uint32_t)sh[jj][c0 + 2*i] | ((uint32_t)sh[jj][c0 + 2*i + 1] << 16);
            b[i] = (uint32_t)sl[jj][c0 + 2*i] | ((uint32_t)sl[jj][c0 + 2*i + 1] << 16);
        }
        *reinterpret_cast<uint4*>(&g_xh[base]) = make_uint4(a[0], a[1], a[2], a[3]);
        *reinterpret_cast<uint4*>(&g_xl[base]) = make_uint4(b[0], b[1], b[2], b[3]);
    }
}

// weights -> [conv][tap][half][ci][co] bf16
__global__ void prep_w(const float* __restrict__ w1, const float* __restrict__ w2) {
    int idx = blockIdx.x * 256 + threadIdx.x;
    if (idx >= 2 * 9 * 64 * 64) return;
    int conv = idx / 36864;
    int r    = idx % 36864;
    int tap  = r / 4096;
    int r2   = r % 4096;
    int co = r2 >> 6, ci = r2 & 63;
    const float* w = conv ? w2 : w1;
    float v = w[(co * 64 + ci) * 9 + tap];
    __nv_bfloat16 h = __float2bfloat16(v);
    __nv_bfloat16 l = __float2bfloat16(v - __bfloat162float(h));
    size_t base = (size_t)((conv * 9 + tap) * 2) * 4096 + ci * 64 + co;
    g_w[base]        = __bfloat16_as_ushort(h);
    g_w[base + 4096] = __bfloat16_as_ushort(l);
}

// fill reflect-padding ring of g_oh/g_ol from interior (after conv1)
__global__ void ring_fix() {
    int p = blockIdx.x * 256 + threadIdx.x;
    if (p >= PW * PW) return;
    int yp = p / PW, xp = p % PW;
    if (yp >= 2 && yp < PW - 2 && xp >= 2 && xp < PW - 2) return;
    int sy = reflect512(yp - 2) + 2;
    int sx = reflect512(xp - 2) + 2;
    size_t d = (size_t)p * 64;
    size_t s = ((size_t)sy * PW + sx) * 64;
    uint4* dh = reinterpret_cast<uint4*>(&g_oh[d]);
    uint4* dl = reinterpret_cast<uint4*>(&g_ol[d]);
    const uint4* shp = reinterpret_cast<const uint4*>(&g_oh[s]);
    const uint4* slp = reinterpret_cast<const uint4*>(&g_ol[s]);
    #pragma unroll
    for (int i = 0; i < 8; i++) { dh[i] = shp[i]; dl[i] = slp[i]; }
}

// ------------------------- conv via warp MMA (HMMA) --------------------------
// MODE 1: input g_xh/g_xl -> g_oh/g_ol = split( md ? gelu(conv+b1) : x )
// MODE 2: input g_oh/g_ol -> d_out[sd] = gelu(conv+b2) + x
template <int MODE>
__global__ void __launch_bounds__(128, 3) conv_mma(
    const float* __restrict__ xres,
    const float* __restrict__ bias,
    const float* __restrict__ mask,
    float* __restrict__ out)
{
    extern __shared__ __align__(16) char smem[];
    const uint32_t sb = smem_u32(smem);
    const int tid = threadIdx.x;
    const int warp = tid >> 5, lane = tid & 31;
    const int x0 = blockIdx.x * MPX;
    const int y  = blockIdx.y;

    const __nv_bfloat16* xh = (MODE == 1) ? g_xh : g_oh;
    const __nv_bfloat16* xl = (MODE == 1) ? g_xl : g_ol;
    const ushort_t* wbase = g_w + (size_t)((MODE == 1 ? 0 : 9) * 2) * 4096;

    // per-lane ldmatrix offsets
    const uint32_t a_off = (uint32_t)(lane & 15) * ASTRIDE + (uint32_t)(lane >> 4) * 16;
    const uint32_t b_off = (uint32_t)((lane & 7) + ((lane >> 3) & 1) * 8) * ASTRIDE
                         + (uint32_t)(lane >> 4) * 16;

    float acc[2][8][4];
    #pragma unroll
    for (int mt = 0; mt < 2; mt++)
        #pragma unroll
        for (int nt = 0; nt < 8; nt++)
            #pragma unroll
            for (int i = 0; i < 4; i++) acc[mt][nt][i] = 0.0f;

    for (int dyi = 0; dyi < 3; dyi++) {
        __syncthreads();   // A buffer safe to overwrite
        // ---- stage A: padded row y + 2*dyi, cols x0 .. x0+131, hi & lo ----
        {
            const size_t rowb = ((size_t)(y + 2 * dyi) * PW + x0) * 64;
            const uint4* srch = reinterpret_cast<const uint4*>(&xh[rowb]);
            const uint4* srcl = reinterpret_cast<const uint4*>(&xl[rowb]);
            for (int i = tid; i < 132 * 8; i += 128) {
                int px = i >> 3, seg = i & 7;
                *reinterpret_cast<uint4*>(smem + SM_AH + px * ASTRIDE + seg * 16) = srch[i];
                *reinterpret_cast<uint4*>(smem + SM_AL + px * ASTRIDE + seg * 16) = srcl[i];
            }
        }
        for (int dxi = 0; dxi < 3; dxi++) {
            const int tap = dyi * 3 + dxi;
            __syncthreads();   // B buffer safe; also publishes A on dxi==0
            // ---- stage B: [ci][co] hi & lo ----
            {
                const uint4* srch = reinterpret_cast<const uint4*>(wbase + (size_t)(tap * 2) * 4096);
                const uint4* srcl = reinterpret_cast<const uint4*>(wbase + (size_t)(tap * 2 + 1) * 4096);
                for (int i = tid; i < 64 * 8; i += 128) {
                    int ci = i >> 3, seg = i & 7;
                    *reinterpret_cast<uint4*>(smem + SM_BH + ci * ASTRIDE + seg * 16) = srch[i];
                    *reinterpret_cast<uint4*>(smem + SM_BL + ci * ASTRIDE + seg * 16) = srcl[i];
                }
            }
            __syncthreads();

            // ---- GEMM: this tap, dx = 2*dxi ----
            const uint32_t am0 = sb + SM_AH + (uint32_t)(32 * warp + 2 * dxi) * ASTRIDE + a_off;
            const uint32_t al0 = am0 + (SM_AL - SM_AH);
            #pragma unroll
            for (int kc = 0; kc < 64; kc += 16) {
                uint32_t ah0[4], ah1[4], av0[4], av1[4];
                ldsm4(ah0, am0 + kc * 2);
                ldsm4(ah1, am0 + 16 * ASTRIDE + kc * 2);
                ldsm4(av0, al0 + kc * 2);
                ldsm4(av1, al0 + 16 * ASTRIDE + kc * 2);
                const uint32_t bbase = sb + SM_BH + (uint32_t)kc * ASTRIDE + b_off;
                #pragma unroll
                for (int nb = 0; nb < 4; nb++) {
                    uint32_t bh[4], bl[4];
                    ldsm4t(bh, bbase + nb * 32);
                    ldsm4t(bl, bbase + (SM_BL - SM_BH) + nb * 32);
                    // hh
                    mma16816(acc[0][2*nb],   ah0, bh[0], bh[1]);
                    mma16816(acc[0][2*nb+1], ah0, bh[2], bh[3]);
                    mma16816(acc[1][2*nb],   ah1, bh[0], bh[1]);
                    mma16816(acc[1][2*nb+1], ah1, bh[2], bh[3]);
                    // hl
                    mma16816(acc[0][2*nb],   ah0, bl[0], bl[1]);
                    mma16816(acc[0][2*nb+1], ah0, bl[2], bl[3]);
                    mma16816(acc[1][2*nb],   ah1, bl[0], bl[1]);
                    mma16816(acc[1][2*nb+1], ah1, bl[2], bl[3]);
                    // lh
                    mma16816(acc[0][2*nb],   av0, bh[0], bh[1]);
                    mma16816(acc[0][2*nb+1], av0, bh[2], bh[3]);
                    mma16816(acc[1][2*nb],   av1, bh[0], bh[1]);
                    mma16816(acc[1][2*nb+1], av1, bh[2], bh[3]);
                }
            }
        }
    }

    // ---- epilogue: fragments -> smem (pixel-major), then write out ----
    __syncthreads();            // everyone done reading A/B smem
    float* sepi = reinterpret_cast<float*>(smem);
    #pragma unroll
    for (int mt = 0; mt < 2; mt++) {
        const int r = 32 * warp + 16 * mt + (lane >> 2);
        #pragma unroll
        for (int nt = 0; nt < 8; nt++) {
            const int c = 8 * nt + 2 * (lane & 3);
            sepi[r * EPI_STRIDE + c]           = acc[mt][nt][0];
            sepi[r * EPI_STRIDE + c + 1]       = acc[mt][nt][1];
            sepi[(r + 8) * EPI_STRIDE + c]     = acc[mt][nt][2];
            sepi[(r + 8) * EPI_STRIDE + c + 1] = acc[mt][nt][3];
        }
    }
    __syncwarp();

    const int m = 32 * warp + lane;     // local pixel
    const int x = x0 + m;
    const int p = y * WW + x;
    const float* arow = &sepi[m * EPI_STRIDE];

    if (MODE == 1) {
        const bool md = (g_md_[p] != 0);
        const size_t ob = ((size_t)(y + 2) * PW + (x + 2)) * 64;
        uint32_t oh[32], ol[32];
        #pragma unroll
        for (int j = 0; j < 32; j++) {
            const int c0 = 2 * j;
            float v0, v1;
            if (md) {
                v0 = gelu_exact(arow[c0]     + __ldg(&bias[c0]));
                v1 = gelu_exact(arow[c0 + 1] + __ldg(&bias[c0 + 1]));
            } else {
                v0 = xres[(size_t)c0 * HW + p];
                v1 = xres[(size_t)(c0 + 1) * HW + p];
            }
            __nv_bfloat16 h0 = __float2bfloat16(v0);
            __nv_bfloat16 l0 = __float2bfloat16(v0 - __bfloat162float(h0));
            __nv_bfloat16 h1 = __float2bfloat16(v1);
            __nv_bfloat16 l1 = __float2bfloat16(v1 - __bfloat162float(h1));
            oh[j] = (uint32_t)__bfloat16_as_ushort(h0) | ((uint32_t)__bfloat16_as_ushort(h1) << 16);
            ol[j] = (uint32_t)__bfloat16_as_ushort(l0) | ((uint32_t)__bfloat16_as_ushort(l1) << 16);
        }
        uint4* dh = reinterpret_cast<uint4*>(&g_oh[ob]);
        uint4* dl = reinterpret_cast<uint4*>(&g_ol[ob]);
        #pragma unroll
        for (int i = 0; i < 8; i++) {
            dh[i] = make_uint4(oh[4*i], oh[4*i+1], oh[4*i+2], oh[4*i+3]);
            dl[i] = make_uint4(ol[4*i], ol[4*i+1], ol[4*i+2], ol[4*i+3]);
        }
    } else {
        if (mask[p] > 0.5f) {
            #pragma unroll 8
            for (int c = 0; c < 64; c++) {
                const size_t o = (size_t)c * HW + p;
                out[o] = gelu_exact(arow[c] + __ldg(&bias[c])) + xres[o];
            }
        }
    }
}

// ------------------------- depthwise path ------------------------------------
__global__ void dw_kernel(
    const float* __restrict__ x,
    const float* __restrict__ w3,
    const float* __restrict__ b3,
    const float* __restrict__ mask,
    float* __restrict__ out)
{
    int gx = blockIdx.x * 256 + threadIdx.x;
    int gy = blockIdx.y;
    int c  = blockIdx.z;
    int p  = gy * WW + gx;
    if (mask[p] > 0.5f) return;

    const float* wc = w3 + c * 9;
    const float* xc = x + (size_t)c * HW;
    float a = 0.0f;
    #pragma unroll
    for (int k = 0; k < 9; k++) {
        int yy = reflect512(gy + (k / 3) * 2 - 2);
        int xx = reflect512(gx + (k % 3) * 2 - 2);
        a = fmaf(xc[yy * WW + xx], wc[k], a);
    }
    out[(size_t)c * HW + p] = gelu_exact(a + b3[c]) + xc[p];
}

// ------------------------- launch --------------------------------------------
extern "C" void kernel_launch(void* const* d_in, const int* in_sizes, int n_in,
                              void* d_out, int out_size) {
    const float* x    = (const float*)d_in[0];
    const float* mask = (const float*)d_in[1];
    const float* w1   = (const float*)d_in[2];
    const float* b1   = (const float*)d_in[3];
    const float* w2   = (const float*)d_in[4];
    const float* b2   = (const float*)d_in[5];
    const float* w3   = (const float*)d_in[6];
    const float* b3   = (const float*)d_in[7];
    float* out = (float*)d_out;

    static bool attr_set = false;
    if (!attr_set) {
        cudaFuncSetAttribute(conv_mma<1>,
            cudaFuncAttributeMaxDynamicSharedMemorySize, SM_TOTAL);
        cudaFuncSetAttribute(conv_mma<2>,
            cudaFuncAttributeMaxDynamicSharedMemorySize, SM_TOTAL);
        attr_set = true;
    }

    md_kernel<<<dim3(WW / 32, HH / 8), dim3(32, 8)>>>(mask);
    prep_w<<<(2 * 9 * 64 * 64 + 255) / 256, 256>>>(w1, w2);
    prep_x<<<dim3((PW + 31) / 32, PW), 256>>>(x);

    dim3 cgrid(WW / MPX, HH);   // 4 x 512

    conv_mma<1><<<cgrid, 128, SM_TOTAL>>>(x, b1, mask, out);
    ring_fix<<<(PW * PW + 255) / 256, 256>>>();
    conv_mma<2><<<cgrid, 128, SM_TOTAL>>>(x, b2, mask, out);

    dw_kernel<<<dim3(WW / 256, HH, CC), 256>>>(x, w3, b3, mask, out);
}

// round 8
// speedup vs baseline: 3.4343x; 1.2081x over previous
#include <cuda_runtime.h>
#include <cuda_fp16.h>
#include <math.h>
#include <stdint.h>

#define HH 512
#define WW 512
#define CC 64
#define HW (HH*WW)
#define PW 516                 // padded H/W (reflect pad 2 materialized)
#define MPX 256                // pixels per CTA tile
#define NTHR 256

// smem layout (bytes)
#define ASTRIDE 144            // 64 ch * 2B = 128B payload, padded (ldmatrix conflict-free)
#define APX 260                // staged pixels per row (256 + halo 4)
#define SM_AH   0
#define SM_AL   (SM_AH + APX * ASTRIDE)        // 37440
#define SM_B    (SM_AL + APX * ASTRIDE)        // 74880
#define SM_TOTAL (SM_B + 64 * ASTRIDE)         // 84096
#define EPI_STRIDE 65                          // floats; epi buffer aliases A region

typedef unsigned short ushort_t;

// ------------------------- device globals (no allocation) -------------------
__device__ __half g_xh[(size_t)PW * PW * CC];
__device__ __half g_xl[(size_t)PW * PW * CC];
__device__ __half g_oh[(size_t)PW * PW * CC];
__device__ __half g_ol[(size_t)PW * PW * CC];
__device__ ushort_t g_w[2 * 9 * 4096];         // [conv][tap][ci*64+co] fp16 hi only
__device__ unsigned char g_md_[HW];

// ------------------------- helpers ------------------------------------------
__device__ __forceinline__ int reflect512(int i) {
    i = abs(i);
    return min(i, 1022 - i);
}
__device__ __forceinline__ float gelu_exact(float v) {
    return 0.5f * v * (1.0f + erff(v * 0.70710678118654752f));
}
__device__ __forceinline__ uint32_t smem_u32(const void* p) {
    uint32_t a;
    asm("{ .reg .u64 t; cvta.to.shared.u64 t, %1; cvt.u32.u64 %0, t; }" : "=r"(a) : "l"(p));
    return a;
}
__device__ __forceinline__ void ldsm4(uint32_t (&r)[4], uint32_t addr) {
    asm volatile("ldmatrix.sync.aligned.m8n8.x4.shared.b16 {%0,%1,%2,%3}, [%4];"
                 : "=r"(r[0]), "=r"(r[1]), "=r"(r[2]), "=r"(r[3]) : "r"(addr));
}
__device__ __forceinline__ void ldsm4t(uint32_t (&r)[4], uint32_t addr) {
    asm volatile("ldmatrix.sync.aligned.m8n8.x4.trans.shared.b16 {%0,%1,%2,%3}, [%4];"
                 : "=r"(r[0]), "=r"(r[1]), "=r"(r[2]), "=r"(r[3]) : "r"(addr));
}
__device__ __forceinline__ void mma16816(float (&d)[4], const uint32_t (&a)[4],
                                         uint32_t b0, uint32_t b1) {
    asm volatile(
        "mma.sync.aligned.m16n8k16.row.col.f32.f16.f16.f32 "
        "{%0,%1,%2,%3}, {%4,%5,%6,%7}, {%8,%9}, {%0,%1,%2,%3};"
        : "+f"(d[0]), "+f"(d[1]), "+f"(d[2]), "+f"(d[3])
        : "r"(a[0]), "r"(a[1]), "r"(a[2]), "r"(a[3]), "r"(b0), "r"(b1));
}

// ------------------------- prepasses -----------------------------------------
__global__ void md_kernel(const float* __restrict__ mask) {
    int x = blockIdx.x * 32 + threadIdx.x;
    int y = blockIdx.y * 8 + threadIdx.y;
    float m = 0.0f;
    #pragma unroll
    for (int dy = -2; dy <= 2; dy++) {
        int yy = y + dy;
        if (yy < 0 || yy >= HH) continue;
        #pragma unroll
        for (int dx = -2; dx <= 2; dx++) {
            int xx = x + dx;
            if (xx < 0 || xx >= WW) continue;
            m = fmaxf(m, mask[yy * WW + xx]);
        }
    }
    g_md_[y * WW + x] = (m > 0.5f) ? 1 : 0;
}

// x (NCHW fp32) -> padded NHWC fp16 hi/lo
__global__ void prep_x(const float* __restrict__ x) {
    __shared__ ushort_t sh[32][66];
    __shared__ ushort_t sl[32][66];
    const int yp  = blockIdx.y;
    const int xp0 = blockIdx.x * 32;
    const int tid = threadIdx.x;
    const int warp = tid >> 5, lane = tid & 31;
    const int ry = reflect512(yp - 2);
    const int xp = xp0 + lane;
    const int rx = reflect512((xp < PW ? xp : PW - 1) - 2);
    #pragma unroll
    for (int q = 0; q < 8; q++) {
        int ci = warp * 8 + q;
        float v = x[(size_t)ci * HW + (size_t)ry * WW + rx];
        __half h = __float2half_rn(v);
        __half l = __float2half_rn(v - __half2float(h));
        sh[lane][ci] = __half_as_ushort(h);
        sl[lane][ci] = __half_as_ushort(l);
    }
    __syncthreads();
    const int jj = tid >> 3, c0 = (tid & 7) * 8;
    const int xpw = xp0 + jj;
    if (xpw < PW) {
        size_t base = ((size_t)yp * PW + xpw) * 64 + c0;
        uint32_t a[4], b[4];
        #pragma unroll
        for (int i = 0; i < 4; i++) {
            a[i] = (uint32_t)sh[jj][c0 + 2*i] | ((uint32_t)sh[jj][c0 + 2*i + 1] << 16);
            b[i] = (uint32_t)sl[jj][c0 + 2*i] | ((uint32_t)sl[jj][c0 + 2*i + 1] << 16);
        }
        *reinterpret_cast<uint4*>(&g_xh[base]) = make_uint4(a[0], a[1], a[2], a[3]);
        *reinterpret_cast<uint4*>(&g_xl[base]) = make_uint4(b[0], b[1], b[2], b[3]);
    }
}

// weights -> [conv][tap][ci][co] fp16 (hi only)
__global__ void prep_w(const float* __restrict__ w1, const float* __restrict__ w2) {
    int idx = blockIdx.x * 256 + threadIdx.x;
    if (idx >= 2 * 9 * 64 * 64) return;
    int conv = idx / 36864;
    int r    = idx % 36864;
    int tap  = r / 4096;
    int r2   = r % 4096;
    int co = r2 >> 6, ci = r2 & 63;
    const float* w = conv ? w2 : w1;
    float v = w[(co * 64 + ci) * 9 + tap];
    g_w[(size_t)(conv * 9 + tap) * 4096 + ci * 64 + co] =
        __half_as_ushort(__float2half_rn(v));
}

// fill reflect-padding ring of g_oh/g_ol from interior (after conv1)
__global__ void ring_fix() {
    int p = blockIdx.x * 256 + threadIdx.x;
    if (p >= PW * PW) return;
    int yp = p / PW, xp = p % PW;
    if (yp >= 2 && yp < PW - 2 && xp >= 2 && xp < PW - 2) return;
    int sy = reflect512(yp - 2) + 2;
    int sx = reflect512(xp - 2) + 2;
    size_t d = (size_t)p * 64;
    size_t s = ((size_t)sy * PW + sx) * 64;
    uint4* dh = reinterpret_cast<uint4*>(&g_oh[d]);
    uint4* dl = reinterpret_cast<uint4*>(&g_ol[d]);
    const uint4* shp = reinterpret_cast<const uint4*>(&g_oh[s]);
    const uint4* slp = reinterpret_cast<const uint4*>(&g_ol[s]);
    #pragma unroll
    for (int i = 0; i < 8; i++) { dh[i] = shp[i]; dl[i] = slp[i]; }
}

// ------------------------- conv via warp MMA (fp16, 2-pass) ------------------
// MODE 1: input g_xh/g_xl -> g_oh/g_ol = split( md ? gelu(conv+b1) : x )
// MODE 2: input g_oh/g_ol -> d_out[sd] = gelu(conv+b2) + x
template <int MODE>
__global__ void __launch_bounds__(NTHR, 2) conv_mma(
    const float* __restrict__ xres,
    const float* __restrict__ bias,
    const float* __restrict__ mask,
    float* __restrict__ out)
{
    extern __shared__ __align__(16) char smem[];
    const uint32_t sb = smem_u32(smem);
    const int tid = threadIdx.x;
    const int warp = tid >> 5, lane = tid & 31;
    const int x0 = blockIdx.x * MPX;
    const int y  = blockIdx.y;

    const __half* xh = (MODE == 1) ? g_xh : g_oh;
    const __half* xl = (MODE == 1) ? g_xl : g_ol;
    const ushort_t* wbase = g_w + (size_t)((MODE == 1) ? 0 : 9) * 4096;

    const uint32_t a_off = (uint32_t)(lane & 15) * ASTRIDE + (uint32_t)(lane >> 4) * 16;
    const uint32_t b_off = (uint32_t)((lane & 7) + ((lane >> 3) & 1) * 8) * ASTRIDE
                         + (uint32_t)(lane >> 4) * 16;

    float acc[2][8][4];
    #pragma unroll
    for (int mt = 0; mt < 2; mt++)
        #pragma unroll
        for (int nt = 0; nt < 8; nt++)
            #pragma unroll
            for (int i = 0; i < 4; i++) acc[mt][nt][i] = 0.0f;

    for (int dyi = 0; dyi < 3; dyi++) {
        __syncthreads();   // A buffer safe to overwrite
        // ---- stage A: padded row y + 2*dyi, APX px, hi & lo ----
        {
            const size_t rowb = ((size_t)(y + 2 * dyi) * PW + x0) * 64;
            const uint4* srch = reinterpret_cast<const uint4*>(&xh[rowb]);
            const uint4* srcl = reinterpret_cast<const uint4*>(&xl[rowb]);
            for (int i = tid; i < APX * 8; i += NTHR) {
                int px = i >> 3, seg = i & 7;
                *reinterpret_cast<uint4*>(smem + SM_AH + px * ASTRIDE + seg * 16) = srch[i];
                *reinterpret_cast<uint4*>(smem + SM_AL + px * ASTRIDE + seg * 16) = srcl[i];
            }
        }
        for (int dxi = 0; dxi < 3; dxi++) {
            const int tap = dyi * 3 + dxi;
            __syncthreads();   // B safe; publishes A on dxi==0
            // ---- stage B: [ci][co] fp16 hi ----
            {
                const uint4* src = reinterpret_cast<const uint4*>(wbase + (size_t)tap * 4096);
                for (int i = tid; i < 64 * 8; i += NTHR) {
                    int ci = i >> 3, seg = i & 7;
                    *reinterpret_cast<uint4*>(smem + SM_B + ci * ASTRIDE + seg * 16) = src[i];
                }
            }
            __syncthreads();

            // ---- GEMM: this tap ----
            const uint32_t am0 = sb + SM_AH + (uint32_t)(32 * warp + 2 * dxi) * ASTRIDE + a_off;
            const uint32_t al0 = am0 + (SM_AL - SM_AH);
            #pragma unroll
            for (int kc = 0; kc < 64; kc += 16) {
                uint32_t ah0[4], ah1[4], av0[4], av1[4];
                ldsm4(ah0, am0 + kc * 2);
                ldsm4(ah1, am0 + 16 * ASTRIDE + kc * 2);
                ldsm4(av0, al0 + kc * 2);
                ldsm4(av1, al0 + 16 * ASTRIDE + kc * 2);
                const uint32_t bbase = sb + SM_B + (uint32_t)kc * ASTRIDE + b_off;
                #pragma unroll
                for (int nb = 0; nb < 4; nb++) {
                    uint32_t bh[4];
                    ldsm4t(bh, bbase + nb * 32);
                    // hi pass
                    mma16816(acc[0][2*nb],   ah0, bh[0], bh[1]);
                    mma16816(acc[0][2*nb+1], ah0, bh[2], bh[3]);
                    mma16816(acc[1][2*nb],   ah1, bh[0], bh[1]);
                    mma16816(acc[1][2*nb+1], ah1, bh[2], bh[3]);
                    // A-lo pass
                    mma16816(acc[0][2*nb],   av0, bh[0], bh[1]);
                    mma16816(acc[0][2*nb+1], av0, bh[2], bh[3]);
                    mma16816(acc[1][2*nb],   av1, bh[0], bh[1]);
                    mma16816(acc[1][2*nb+1], av1, bh[2], bh[3]);
                }
            }
        }
    }

    // ---- epilogue: fragments -> smem (pixel-major), then write out ----
    __syncthreads();            // everyone done reading A/B smem
    float* sepi = reinterpret_cast<float*>(smem);
    #pragma unroll
    for (int mt = 0; mt < 2; mt++) {
        const int r = 32 * warp + 16 * mt + (lane >> 2);
        #pragma unroll
        for (int nt = 0; nt < 8; nt++) {
            const int c = 8 * nt + 2 * (lane & 3);
            sepi[r * EPI_STRIDE + c]           = acc[mt][nt][0];
            sepi[r * EPI_STRIDE + c + 1]       = acc[mt][nt][1];
            sepi[(r + 8) * EPI_STRIDE + c]     = acc[mt][nt][2];
            sepi[(r + 8) * EPI_STRIDE + c + 1] = acc[mt][nt][3];
        }
    }
    __syncwarp();

    const int m = tid;                 // local pixel (warp w owns rows 32w..32w+31 = its lanes)
    const int x = x0 + m;
    const int p = y * WW + x;
    const float* arow = &sepi[m * EPI_STRIDE];

    if (MODE == 1) {
        const bool md = (g_md_[p] != 0);
        const size_t ob = ((size_t)(y + 2) * PW + (x + 2)) * 64;
        uint4* dh = reinterpret_cast<uint4*>(&g_oh[ob]);
        uint4* dl = reinterpret_cast<uint4*>(&g_ol[ob]);
        if (md) {
            uint32_t oh[32], ol[32];
            #pragma unroll
            for (int j = 0; j < 32; j++) {
                const int c0 = 2 * j;
                float v0 = gelu_exact(arow[c0]     + __ldg(&bias[c0]));
                float v1 = gelu_exact(arow[c0 + 1] + __ldg(&bias[c0 + 1]));
                __half h0 = __float2half_rn(v0);
                __half l0 = __float2half_rn(v0 - __half2float(h0));
                __half h1 = __float2half_rn(v1);
                __half l1 = __float2half_rn(v1 - __half2float(h1));
                oh[j] = (uint32_t)__half_as_ushort(h0) | ((uint32_t)__half_as_ushort(h1) << 16);
                ol[j] = (uint32_t)__half_as_ushort(l0) | ((uint32_t)__half_as_ushort(l1) << 16);
            }
            #pragma unroll
            for (int i = 0; i < 8; i++) {
                dh[i] = make_uint4(oh[4*i], oh[4*i+1], oh[4*i+2], oh[4*i+3]);
                dl[i] = make_uint4(ol[4*i], ol[4*i+1], ol[4*i+2], ol[4*i+3]);
            }
        } else {
            const uint4* shp = reinterpret_cast<const uint4*>(&g_xh[ob]);
            const uint4* slp = reinterpret_cast<const uint4*>(&g_xl[ob]);
            #pragma unroll
            for (int i = 0; i < 8; i++) { dh[i] = shp[i]; dl[i] = slp[i]; }
        }
    } else {
        if (mask[p] > 0.5f) {
            #pragma unroll 8
            for (int c = 0; c < 64; c++) {
                const size_t o = (size_t)c * HW + p;
                out[o] = gelu_exact(arow[c] + __ldg(&bias[c])) + xres[o];
            }
        }
    }
}

// ------------------------- depthwise path ------------------------------------
__global__ void dw_kernel(
    const float* __restrict__ x,
    const float* __restrict__ w3,
    const float* __restrict__ b3,
    const float* __restrict__ mask,
    float* __restrict__ out)
{
    int gx = blockIdx.x * 256 + threadIdx.x;
    int gy = blockIdx.y;
    int c  = blockIdx.z;
    int p  = gy * WW + gx;
    if (mask[p] > 0.5f) return;

    const float* wc = w3 + c * 9;
    const float* xc = x + (size_t)c * HW;
    float a = 0.0f;
    #pragma unroll
    for (int k = 0; k < 9; k++) {
        int yy = reflect512(gy + (k / 3) * 2 - 2);
        int xx = reflect512(gx + (k % 3) * 2 - 2);
        a = fmaf(xc[yy * WW + xx], wc[k], a);
    }
    out[(size_t)c * HW + p] = gelu_exact(a + b3[c]) + xc[p];
}

// ------------------------- launch --------------------------------------------
extern "C" void kernel_launch(void* const* d_in, const int* in_sizes, int n_in,
                              void* d_out, int out_size) {
    const float* x    = (const float*)d_in[0];
    const float* mask = (const float*)d_in[1];
    const float* w1   = (const float*)d_in[2];
    const float* b1   = (const float*)d_in[3];
    const float* w2   = (const float*)d_in[4];
    const float* b2   = (const float*)d_in[5];
    const float* w3   = (const float*)d_in[6];
    const float* b3   = (const float*)d_in[7];
    float* out = (float*)d_out;

    static bool attr_set = false;
    if (!attr_set) {
        cudaFuncSetAttribute(conv_mma<1>,
            cudaFuncAttributeMaxDynamicSharedMemorySize, SM_TOTAL);
        cudaFuncSetAttribute(conv_mma<2>,
            cudaFuncAttributeMaxDynamicSharedMemorySize, SM_TOTAL);
        attr_set = true;
    }

    md_kernel<<<dim3(WW / 32, HH / 8), dim3(32, 8)>>>(mask);
    prep_w<<<(2 * 9 * 64 * 64 + 255) / 256, 256>>>(w1, w2);
    prep_x<<<dim3((PW + 31) / 32, PW), 256>>>(x);

    dim3 cgrid(WW / MPX, HH);   // 2 x 512

    conv_mma<1><<<cgrid, NTHR, SM_TOTAL>>>(x, b1, mask, out);
    ring_fix<<<(PW * PW + 255) / 256, 256>>>();
    conv_mma<2><<<cgrid, NTHR, SM_TOTAL>>>(x, b2, mask, out);

    dw_kernel<<<dim3(WW / 256, HH, CC), 256>>>(x, w3, b3, mask, out);
}

// round 9
// speedup vs baseline: 4.6224x; 1.3459x over previous
#include <cuda_runtime.h>
#include <cuda_fp16.h>
#include <math.h>
#include <stdint.h>

#define HH 512
#define WW 512
#define CC 64
#define HW (HH*WW)
#define PW 516                 // padded H/W (reflect pad 2 materialized)
#define MPX 256                // pixels per CTA tile
#define NTHR 256

// smem layout (bytes)
#define ASTRIDE 144            // 64 ch * 2B = 128B payload, padded (ldmatrix conflict-free)
#define APX 260                // staged pixels per row (256 + halo 4)
#define SM_A    0
#define SM_B    (APX * ASTRIDE)                 // 37440
#define BSLOT   (64 * ASTRIDE)                  // 9216 per tap
#define EPI_STRIDE 65                           // floats; epi aliases whole smem
#define SM_TOTAL (MPX * EPI_STRIDE * 4)         // 66560 >= 37440 + 3*9216

typedef unsigned short ushort_t;

// ------------------------- device globals (no allocation) -------------------
__device__ __half g_xh[(size_t)PW * PW * CC];   // x, padded NHWC fp16
__device__ __half g_oh[(size_t)PW * PW * CC];   // x_ori, padded NHWC fp16
__device__ ushort_t g_w[2 * 9 * 4096];          // [conv][tap][ci*64+co] fp16
__device__ unsigned char g_md_[HW];

// ------------------------- helpers ------------------------------------------
__device__ __forceinline__ int reflect512(int i) {
    i = abs(i);
    return min(i, 1022 - i);
}
__device__ __forceinline__ float gelu_exact(float v) {
    return 0.5f * v * (1.0f + erff(v * 0.70710678118654752f));
}
__device__ __forceinline__ uint32_t smem_u32(const void* p) {
    uint32_t a;
    asm("{ .reg .u64 t; cvta.to.shared.u64 t, %1; cvt.u32.u64 %0, t; }" : "=r"(a) : "l"(p));
    return a;
}
__device__ __forceinline__ void ldsm4(uint32_t (&r)[4], uint32_t addr) {
    asm volatile("ldmatrix.sync.aligned.m8n8.x4.shared.b16 {%0,%1,%2,%3}, [%4];"
                 : "=r"(r[0]), "=r"(r[1]), "=r"(r[2]), "=r"(r[3]) : "r"(addr));
}
__device__ __forceinline__ void ldsm4t(uint32_t (&r)[4], uint32_t addr) {
    asm volatile("ldmatrix.sync.aligned.m8n8.x4.trans.shared.b16 {%0,%1,%2,%3}, [%4];"
                 : "=r"(r[0]), "=r"(r[1]), "=r"(r[2]), "=r"(r[3]) : "r"(addr));
}
__device__ __forceinline__ void mma16816(float (&d)[4], const uint32_t (&a)[4],
                                         uint32_t b0, uint32_t b1) {
    asm volatile(
        "mma.sync.aligned.m16n8k16.row.col.f32.f16.f16.f32 "
        "{%0,%1,%2,%3}, {%4,%5,%6,%7}, {%8,%9}, {%0,%1,%2,%3};"
        : "+f"(d[0]), "+f"(d[1]), "+f"(d[2]), "+f"(d[3])
        : "r"(a[0]), "r"(a[1]), "r"(a[2]), "r"(a[3]), "r"(b0), "r"(b1));
}

// ------------------------- prepasses -----------------------------------------
__global__ void md_kernel(const float* __restrict__ mask) {
    int x = blockIdx.x * 32 + threadIdx.x;
    int y = blockIdx.y * 8 + threadIdx.y;
    float m = 0.0f;
    #pragma unroll
    for (int dy = -2; dy <= 2; dy++) {
        int yy = y + dy;
        if (yy < 0 || yy >= HH) continue;
        #pragma unroll
        for (int dx = -2; dx <= 2; dx++) {
            int xx = x + dx;
            if (xx < 0 || xx >= WW) continue;
            m = fmaxf(m, mask[yy * WW + xx]);
        }
    }
    g_md_[y * WW + x] = (m > 0.5f) ? 1 : 0;
}

// x (NCHW fp32) -> padded NHWC fp16
__global__ void prep_x(const float* __restrict__ x) {
    __shared__ ushort_t sh[32][66];
    const int yp  = blockIdx.y;
    const int xp0 = blockIdx.x * 32;
    const int tid = threadIdx.x;
    const int warp = tid >> 5, lane = tid & 31;
    const int ry = reflect512(yp - 2);
    const int xp = xp0 + lane;
    const int rx = reflect512((xp < PW ? xp : PW - 1) - 2);
    #pragma unroll
    for (int q = 0; q < 8; q++) {
        int ci = warp * 8 + q;
        float v = x[(size_t)ci * HW + (size_t)ry * WW + rx];
        sh[lane][ci] = __half_as_ushort(__float2half_rn(v));
    }
    __syncthreads();
    const int jj = tid >> 3, c0 = (tid & 7) * 8;
    const int xpw = xp0 + jj;
    if (xpw < PW) {
        size_t base = ((size_t)yp * PW + xpw) * 64 + c0;
        uint32_t a[4];
        #pragma unroll
        for (int i = 0; i < 4; i++)
            a[i] = (uint32_t)sh[jj][c0 + 2*i] | ((uint32_t)sh[jj][c0 + 2*i + 1] << 16);
        *reinterpret_cast<uint4*>(&g_xh[base]) = make_uint4(a[0], a[1], a[2], a[3]);
    }
}

// weights -> [conv][tap][ci][co] fp16
__global__ void prep_w(const float* __restrict__ w1, const float* __restrict__ w2) {
    int idx = blockIdx.x * 256 + threadIdx.x;
    if (idx >= 2 * 9 * 64 * 64) return;
    int conv = idx / 36864;
    int r    = idx % 36864;
    int tap  = r / 4096;
    int r2   = r % 4096;
    int co = r2 >> 6, ci = r2 & 63;
    const float* w = conv ? w2 : w1;
    float v = w[(co * 64 + ci) * 9 + tap];
    g_w[(size_t)(conv * 9 + tap) * 4096 + ci * 64 + co] =
        __half_as_ushort(__float2half_rn(v));
}

// fill reflect-padding ring of g_oh from interior (after conv1)
__global__ void ring_fix() {
    int p = blockIdx.x * 256 + threadIdx.x;
    if (p >= PW * PW) return;
    int yp = p / PW, xp = p % PW;
    if (yp >= 2 && yp < PW - 2 && xp >= 2 && xp < PW - 2) return;
    int sy = reflect512(yp - 2) + 2;
    int sx = reflect512(xp - 2) + 2;
    size_t d = (size_t)p * 64;
    size_t s = ((size_t)sy * PW + sx) * 64;
    uint4* dh = reinterpret_cast<uint4*>(&g_oh[d]);
    const uint4* shp = reinterpret_cast<const uint4*>(&g_oh[s]);
    #pragma unroll
    for (int i = 0; i < 8; i++) dh[i] = shp[i];
}

// ------------------------- conv via warp MMA (fp16, single pass) -------------
// MODE 1: input g_xh -> g_oh = fp16( md ? gelu(conv+b1) : x )
// MODE 2: input g_oh -> d_out[sd] = gelu(conv+b2) + x
template <int MODE>
__global__ void __launch_bounds__(NTHR, 2) conv_mma(
    const float* __restrict__ xres,
    const float* __restrict__ bias,
    const float* __restrict__ mask,
    float* __restrict__ out)
{
    extern __shared__ __align__(16) char smem[];
    const uint32_t sb = smem_u32(smem);
    const int tid = threadIdx.x;
    const int warp = tid >> 5, lane = tid & 31;
    const int x0 = blockIdx.x * MPX;
    const int y  = blockIdx.y;

    const __half* xin = (MODE == 1) ? g_xh : g_oh;
    const ushort_t* wbase = g_w + (size_t)((MODE == 1) ? 0 : 9) * 4096;

    const uint32_t a_off = (uint32_t)(lane & 15) * ASTRIDE + (uint32_t)(lane >> 4) * 16;
    const uint32_t b_off = (uint32_t)((lane & 7) + ((lane >> 3) & 1) * 8) * ASTRIDE
                         + (uint32_t)(lane >> 4) * 16;

    float acc[2][8][4];
    #pragma unroll
    for (int mt = 0; mt < 2; mt++)
        #pragma unroll
        for (int nt = 0; nt < 8; nt++)
            #pragma unroll
            for (int i = 0; i < 4; i++) acc[mt][nt][i] = 0.0f;

    for (int dyi = 0; dyi < 3; dyi++) {
        __syncthreads();   // A/B buffers safe to overwrite
        // ---- stage A: padded row y + 2*dyi, APX px ----
        {
            const size_t rowb = ((size_t)(y + 2 * dyi) * PW + x0) * 64;
            const uint4* src = reinterpret_cast<const uint4*>(&xin[rowb]);
            for (int i = tid; i < APX * 8; i += NTHR) {
                int px = i >> 3, seg = i & 7;
                *reinterpret_cast<uint4*>(smem + SM_A + px * ASTRIDE + seg * 16) = src[i];
            }
        }
        // ---- stage B: 3 taps of this dy-row ----
        {
            const uint4* src = reinterpret_cast<const uint4*>(wbase + (size_t)(3 * dyi) * 4096);
            for (int i = tid; i < 3 * 64 * 8; i += NTHR) {
                int slot = i / 512;          // tap within row
                int rem  = i - slot * 512;
                int ci = rem >> 3, seg = rem & 7;
                *reinterpret_cast<uint4*>(smem + SM_B + slot * BSLOT + ci * ASTRIDE + seg * 16) = src[i];
            }
        }
        __syncthreads();

        #pragma unroll
        for (int dxi = 0; dxi < 3; dxi++) {
            const uint32_t am0 = sb + SM_A + (uint32_t)(32 * warp + 2 * dxi) * ASTRIDE + a_off;
            const uint32_t bb  = sb + SM_B + (uint32_t)dxi * BSLOT + b_off;
            #pragma unroll
            for (int kc = 0; kc < 64; kc += 16) {
                uint32_t ah0[4], ah1[4];
                ldsm4(ah0, am0 + kc * 2);
                ldsm4(ah1, am0 + 16 * ASTRIDE + kc * 2);
                const uint32_t bbase = bb + (uint32_t)kc * ASTRIDE;
                #pragma unroll
                for (int nb = 0; nb < 4; nb++) {
                    uint32_t bh[4];
                    ldsm4t(bh, bbase + nb * 32);
                    mma16816(acc[0][2*nb],   ah0, bh[0], bh[1]);
                    mma16816(acc[0][2*nb+1], ah0, bh[2], bh[3]);
                    mma16816(acc[1][2*nb],   ah1, bh[0], bh[1]);
                    mma16816(acc[1][2*nb+1], ah1, bh[2], bh[3]);
                }
            }
        }
    }

    // ---- epilogue: fragments -> smem (pixel-major), then write out ----
    __syncthreads();
    float* sepi = reinterpret_cast<float*>(smem);
    #pragma unroll
    for (int mt = 0; mt < 2; mt++) {
        const int r = 32 * warp + 16 * mt + (lane >> 2);
        #pragma unroll
        for (int nt = 0; nt < 8; nt++) {
            const int c = 8 * nt + 2 * (lane & 3);
            sepi[r * EPI_STRIDE + c]           = acc[mt][nt][0];
            sepi[r * EPI_STRIDE + c + 1]       = acc[mt][nt][1];
            sepi[(r + 8) * EPI_STRIDE + c]     = acc[mt][nt][2];
            sepi[(r + 8) * EPI_STRIDE + c + 1] = acc[mt][nt][3];
        }
    }
    __syncwarp();

    const int m = tid;
    const int x = x0 + m;
    const int p = y * WW + x;
    const float* arow = &sepi[m * EPI_STRIDE];

    if (MODE == 1) {
        const bool md = (g_md_[p] != 0);
        const size_t ob = ((size_t)(y + 2) * PW + (x + 2)) * 64;
        uint4* dh = reinterpret_cast<uint4*>(&g_oh[ob]);
        if (md) {
            uint32_t oh[32];
            #pragma unroll
            for (int j = 0; j < 32; j++) {
                const int c0 = 2 * j;
                float v0 = gelu_exact(arow[c0]     + __ldg(&bias[c0]));
                float v1 = gelu_exact(arow[c0 + 1] + __ldg(&bias[c0 + 1]));
                oh[j] = (uint32_t)__half_as_ushort(__float2half_rn(v0))
                      | ((uint32_t)__half_as_ushort(__float2half_rn(v1)) << 16);
            }
            #pragma unroll
            for (int i = 0; i < 8; i++)
                dh[i] = make_uint4(oh[4*i], oh[4*i+1], oh[4*i+2], oh[4*i+3]);
        } else {
            const uint4* shp = reinterpret_cast<const uint4*>(&g_xh[ob]);
            #pragma unroll
            for (int i = 0; i < 8; i++) dh[i] = shp[i];
        }
    } else {
        if (mask[p] > 0.5f) {
            #pragma unroll 8
            for (int c = 0; c < 64; c++) {
                const size_t o = (size_t)c * HW + p;
                out[o] = gelu_exact(arow[c] + __ldg(&bias[c])) + xres[o];
            }
        }
    }
}

// ------------------------- depthwise path ------------------------------------
__global__ void dw_kernel(
    const float* __restrict__ x,
    const float* __restrict__ w3,
    const float* __restrict__ b3,
    const float* __restrict__ mask,
    float* __restrict__ out)
{
    int gx = blockIdx.x * 256 + threadIdx.x;
    int gy = blockIdx.y;
    int c  = blockIdx.z;
    int p  = gy * WW + gx;
    if (mask[p] > 0.5f) return;

    const float* wc = w3 + c * 9;
    const float* xc = x + (size_t)c * HW;
    float a = 0.0f;
    #pragma unroll
    for (int k = 0; k < 9; k++) {
        int yy = reflect512(gy + (k / 3) * 2 - 2);
        int xx = reflect512(gx + (k % 3) * 2 - 2);
        a = fmaf(xc[yy * WW + xx], wc[k], a);
    }
    out[(size_t)c * HW + p] = gelu_exact(a + b3[c]) + xc[p];
}

// ------------------------- launch --------------------------------------------
extern "C" void kernel_launch(void* const* d_in, const int* in_sizes, int n_in,
                              void* d_out, int out_size) {
    const float* x    = (const float*)d_in[0];
    const float* mask = (const float*)d_in[1];
    const float* w1   = (const float*)d_in[2];
    const float* b1   = (const float*)d_in[3];
    const float* w2   = (const float*)d_in[4];
    const float* b2   = (const float*)d_in[5];
    const float* w3   = (const float*)d_in[6];
    const float* b3   = (const float*)d_in[7];
    float* out = (float*)d_out;

    static bool attr_set = false;
    if (!attr_set) {
        cudaFuncSetAttribute(conv_mma<1>,
            cudaFuncAttributeMaxDynamicSharedMemorySize, SM_TOTAL);
        cudaFuncSetAttribute(conv_mma<2>,
            cudaFuncAttributeMaxDynamicSharedMemorySize, SM_TOTAL);
        attr_set = true;
    }

    md_kernel<<<dim3(WW / 32, HH / 8), dim3(32, 8)>>>(mask);
    prep_w<<<(2 * 9 * 64 * 64 + 255) / 256, 256>>>(w1, w2);
    prep_x<<<dim3((PW + 31) / 32, PW), 256>>>(x);

    dim3 cgrid(WW / MPX, HH);   // 2 x 512

    conv_mma<1><<<cgrid, NTHR, SM_TOTAL>>>(x, b1, mask, out);
    ring_fix<<<(PW * PW + 255) / 256, 256>>>();
    conv_mma<2><<<cgrid, NTHR, SM_TOTAL>>>(x, b2, mask, out);

    dw_kernel<<<dim3(WW / 256, HH, CC), 256>>>(x, w3, b3, mask, out);
}

// round 10
// speedup vs baseline: 5.1975x; 1.1244x over previous
#include <cuda_runtime.h>
#include <cuda_fp16.h>
#include <math.h>
#include <stdint.h>

#define HH 512
#define WW 512
#define CC 64
#define HW (HH*WW)
#define PW 516                 // padded H/W (reflect pad 2 materialized)
#define MPX 128                // pixels per CTA tile
#define NTHR 128

// smem layout (bytes)
#define ASTRIDE 144            // 64 ch * 2B payload, padded (ldmatrix conflict-free)
#define APX 132                // staged pixels per row (128 + halo 4)
#define SM_A    0
#define SM_B    (APX * ASTRIDE)                 // 19008
#define BSLOT   (64 * ASTRIDE)                  // 9216 per tap
#define SM_TOTAL (SM_B + 3 * BSLOT)             // 46656
#define EPI_STRIDE 65                           // floats; epi aliases smem (33280 B)

typedef unsigned short ushort_t;

// ------------------------- device globals (no allocation) -------------------
__device__ __half g_xh[(size_t)PW * PW * CC];   // x, padded NHWC fp16
__device__ __half g_oh[(size_t)PW * PW * CC];   // x_ori, padded NHWC fp16
__device__ ushort_t g_w[2 * 9 * 4096];          // [conv][tap][ci*64+co] fp16
__device__ unsigned char g_md_[HW];

// ------------------------- helpers ------------------------------------------
__device__ __forceinline__ int reflect512(int i) {
    i = abs(i);
    return min(i, 1022 - i);
}
__device__ __forceinline__ float gelu_exact(float v) {
    return 0.5f * v * (1.0f + erff(v * 0.70710678118654752f));
}
__device__ __forceinline__ uint32_t smem_u32(const void* p) {
    uint32_t a;
    asm("{ .reg .u64 t; cvta.to.shared.u64 t, %1; cvt.u32.u64 %0, t; }" : "=r"(a) : "l"(p));
    return a;
}
__device__ __forceinline__ void cp16(uint32_t dst, const void* src) {
    asm volatile("cp.async.ca.shared.global [%0], [%1], 16;" :: "r"(dst), "l"(src));
}
__device__ __forceinline__ void cp_commit_wait() {
    asm volatile("cp.async.commit_group;");
    asm volatile("cp.async.wait_group 0;");
}
__device__ __forceinline__ void ldsm4(uint32_t (&r)[4], uint32_t addr) {
    asm volatile("ldmatrix.sync.aligned.m8n8.x4.shared.b16 {%0,%1,%2,%3}, [%4];"
                 : "=r"(r[0]), "=r"(r[1]), "=r"(r[2]), "=r"(r[3]) : "r"(addr));
}
__device__ __forceinline__ void ldsm4t(uint32_t (&r)[4], uint32_t addr) {
    asm volatile("ldmatrix.sync.aligned.m8n8.x4.trans.shared.b16 {%0,%1,%2,%3}, [%4];"
                 : "=r"(r[0]), "=r"(r[1]), "=r"(r[2]), "=r"(r[3]) : "r"(addr));
}
__device__ __forceinline__ void mma16816(float (&d)[4], const uint32_t (&a)[4],
                                         uint32_t b0, uint32_t b1) {
    asm volatile(
        "mma.sync.aligned.m16n8k16.row.col.f32.f16.f16.f32 "
        "{%0,%1,%2,%3}, {%4,%5,%6,%7}, {%8,%9}, {%0,%1,%2,%3};"
        : "+f"(d[0]), "+f"(d[1]), "+f"(d[2]), "+f"(d[3])
        : "r"(a[0]), "r"(a[1]), "r"(a[2]), "r"(a[3]), "r"(b0), "r"(b1));
}

// ------------------------- prepasses -----------------------------------------
__global__ void md_kernel(const float* __restrict__ mask) {
    int x = blockIdx.x * 32 + threadIdx.x;
    int y = blockIdx.y * 8 + threadIdx.y;
    float m = 0.0f;
    #pragma unroll
    for (int dy = -2; dy <= 2; dy++) {
        int yy = y + dy;
        if (yy < 0 || yy >= HH) continue;
        #pragma unroll
        for (int dx = -2; dx <= 2; dx++) {
            int xx = x + dx;
            if (xx < 0 || xx >= WW) continue;
            m = fmaxf(m, mask[yy * WW + xx]);
        }
    }
    g_md_[y * WW + x] = (m > 0.5f) ? 1 : 0;
}

// x (NCHW fp32) -> padded NHWC fp16
__global__ void prep_x(const float* __restrict__ x) {
    __shared__ ushort_t sh[32][66];
    const int yp  = blockIdx.y;
    const int xp0 = blockIdx.x * 32;
    const int tid = threadIdx.x;
    const int warp = tid >> 5, lane = tid & 31;
    const int ry = reflect512(yp - 2);
    const int xp = xp0 + lane;
    const int rx = reflect512((xp < PW ? xp : PW - 1) - 2);
    #pragma unroll
    for (int q = 0; q < 8; q++) {
        int ci = warp * 8 + q;
        float v = x[(size_t)ci * HW + (size_t)ry * WW + rx];
        sh[lane][ci] = __half_as_ushort(__float2half_rn(v));
    }
    __syncthreads();
    const int jj = tid >> 3, c0 = (tid & 7) * 8;
    const int xpw = xp0 + jj;
    if (xpw < PW) {
        size_t base = ((size_t)yp * PW + xpw) * 64 + c0;
        uint32_t a[4];
        #pragma unroll
        for (int i = 0; i < 4; i++)
            a[i] = (uint32_t)sh[jj][c0 + 2*i] | ((uint32_t)sh[jj][c0 + 2*i + 1] << 16);
        *reinterpret_cast<uint4*>(&g_xh[base]) = make_uint4(a[0], a[1], a[2], a[3]);
    }
}

// weights -> [conv][tap][ci][co] fp16
__global__ void prep_w(const float* __restrict__ w1, const float* __restrict__ w2) {
    int idx = blockIdx.x * 256 + threadIdx.x;
    if (idx >= 2 * 9 * 64 * 64) return;
    int conv = idx / 36864;
    int r    = idx % 36864;
    int tap  = r / 4096;
    int r2   = r % 4096;
    int co = r2 >> 6, ci = r2 & 63;
    const float* w = conv ? w2 : w1;
    float v = w[(co * 64 + ci) * 9 + tap];
    g_w[(size_t)(conv * 9 + tap) * 4096 + ci * 64 + co] =
        __half_as_ushort(__float2half_rn(v));
}

// fill reflect-padding ring of g_oh from interior (after conv1)
__global__ void ring_fix() {
    int p = blockIdx.x * 256 + threadIdx.x;
    if (p >= PW * PW) return;
    int yp = p / PW, xp = p % PW;
    if (yp >= 2 && yp < PW - 2 && xp >= 2 && xp < PW - 2) return;
    int sy = reflect512(yp - 2) + 2;
    int sx = reflect512(xp - 2) + 2;
    size_t d = (size_t)p * 64;
    size_t s = ((size_t)sy * PW + sx) * 64;
    uint4* dh = reinterpret_cast<uint4*>(&g_oh[d]);
    const uint4* shp = reinterpret_cast<const uint4*>(&g_oh[s]);
    #pragma unroll
    for (int i = 0; i < 8; i++) dh[i] = shp[i];
}

// ------------------------- conv via warp MMA (fp16, single pass) -------------
// MODE 1: input g_xh -> g_oh = fp16( md ? gelu(conv+b1) : x )
// MODE 2: input g_oh -> d_out[sd] = gelu(conv+b2) + x
template <int MODE>
__global__ void __launch_bounds__(NTHR, 3) conv_mma(
    const float* __restrict__ xres,
    const float* __restrict__ bias,
    const float* __restrict__ mask,
    float* __restrict__ out)
{
    extern __shared__ __align__(16) char smem[];
    const uint32_t sb = smem_u32(smem);
    const int tid = threadIdx.x;
    const int warp = tid >> 5, lane = tid & 31;
    const int x0 = blockIdx.x * MPX;
    const int y  = blockIdx.y;

    const __half* xin = (MODE == 1) ? g_xh : g_oh;
    const ushort_t* wbase = g_w + (size_t)((MODE == 1) ? 0 : 9) * 4096;

    const uint32_t a_off = (uint32_t)(lane & 15) * ASTRIDE + (uint32_t)(lane >> 4) * 16;
    const uint32_t b_off = (uint32_t)((lane & 7) + ((lane >> 3) & 1) * 8) * ASTRIDE
                         + (uint32_t)(lane >> 4) * 16;

    float acc[2][8][4];
    #pragma unroll
    for (int mt = 0; mt < 2; mt++)
        #pragma unroll
        for (int nt = 0; nt < 8; nt++)
            #pragma unroll
            for (int i = 0; i < 4; i++) acc[mt][nt][i] = 0.0f;

    for (int dyi = 0; dyi < 3; dyi++) {
        __syncthreads();   // A/B buffers safe to overwrite
        // ---- stage A: padded row y + 2*dyi, APX px (cp.async) ----
        {
            const char* src = reinterpret_cast<const char*>(
                &xin[((size_t)(y + 2 * dyi) * PW + x0) * 64]);
            #pragma unroll
            for (int it = 0; it < (APX * 8 + NTHR - 1) / NTHR; it++) {
                int i = tid + it * NTHR;
                if (i < APX * 8) {
                    int px = i >> 3, seg = i & 7;
                    cp16(sb + SM_A + px * ASTRIDE + seg * 16, src + i * 16);
                }
            }
        }
        // ---- stage B: 3 taps of this dy-row (cp.async) ----
        {
            const char* src = reinterpret_cast<const char*>(wbase + (size_t)(3 * dyi) * 4096);
            #pragma unroll
            for (int it = 0; it < (3 * 512) / NTHR; it++) {
                int i = tid + it * NTHR;
                int slot = i >> 9;           // tap within row
                int rem  = i & 511;
                int ci = rem >> 3, seg = rem & 7;
                cp16(sb + SM_B + slot * BSLOT + ci * ASTRIDE + seg * 16, src + i * 16);
            }
        }
        cp_commit_wait();
        __syncthreads();

        #pragma unroll
        for (int dxi = 0; dxi < 3; dxi++) {
            const uint32_t am0 = sb + SM_A + (uint32_t)(32 * warp + 2 * dxi) * ASTRIDE + a_off;
            const uint32_t bb  = sb + SM_B + (uint32_t)dxi * BSLOT + b_off;
            #pragma unroll
            for (int kc = 0; kc < 64; kc += 16) {
                uint32_t ah0[4], ah1[4];
                ldsm4(ah0, am0 + kc * 2);
                ldsm4(ah1, am0 + 16 * ASTRIDE + kc * 2);
                const uint32_t bbase = bb + (uint32_t)kc * ASTRIDE;
                #pragma unroll
                for (int nb = 0; nb < 4; nb++) {
                    uint32_t bh[4];
                    ldsm4t(bh, bbase + nb * 32);
                    mma16816(acc[0][2*nb],   ah0, bh[0], bh[1]);
                    mma16816(acc[0][2*nb+1], ah0, bh[2], bh[3]);
                    mma16816(acc[1][2*nb],   ah1, bh[0], bh[1]);
                    mma16816(acc[1][2*nb+1], ah1, bh[2], bh[3]);
                }
            }
        }
    }

    // ---- epilogue: fragments -> smem (pixel-major), then write out ----
    __syncthreads();
    float* sepi = reinterpret_cast<float*>(smem);
    #pragma unroll
    for (int mt = 0; mt < 2; mt++) {
        const int r = 32 * warp + 16 * mt + (lane >> 2);
        #pragma unroll
        for (int nt = 0; nt < 8; nt++) {
            const int c = 8 * nt + 2 * (lane & 3);
            sepi[r * EPI_STRIDE + c]           = acc[mt][nt][0];
            sepi[r * EPI_STRIDE + c + 1]       = acc[mt][nt][1];
            sepi[(r + 8) * EPI_STRIDE + c]     = acc[mt][nt][2];
            sepi[(r + 8) * EPI_STRIDE + c + 1] = acc[mt][nt][3];
        }
    }
    __syncwarp();

    const int m = tid;                 // local pixel (warp w owns px 32w..32w+31)
    const int x = x0 + m;
    const int p = y * WW + x;
    const float* arow = &sepi[m * EPI_STRIDE];

    if (MODE == 1) {
        const bool md = (g_md_[p] != 0);
        const size_t ob = ((size_t)(y + 2) * PW + (x + 2)) * 64;
        uint4* dh = reinterpret_cast<uint4*>(&g_oh[ob]);
        if (md) {
            uint32_t oh[32];
            #pragma unroll
            for (int j = 0; j < 32; j++) {
                const int c0 = 2 * j;
                float v0 = gelu_exact(arow[c0]     + __ldg(&bias[c0]));
                float v1 = gelu_exact(arow[c0 + 1] + __ldg(&bias[c0 + 1]));
                oh[j] = (uint32_t)__half_as_ushort(__float2half_rn(v0))
                      | ((uint32_t)__half_as_ushort(__float2half_rn(v1)) << 16);
            }
            #pragma unroll
            for (int i = 0; i < 8; i++)
                dh[i] = make_uint4(oh[4*i], oh[4*i+1], oh[4*i+2], oh[4*i+3]);
        } else {
            const uint4* shp = reinterpret_cast<const uint4*>(&g_xh[ob]);
            #pragma unroll
            for (int i = 0; i < 8; i++) dh[i] = shp[i];
        }
    } else {
        if (mask[p] > 0.5f) {
            #pragma unroll 8
            for (int c = 0; c < 64; c++) {
                const size_t o = (size_t)c * HW + p;
                out[o] = gelu_exact(arow[c] + __ldg(&bias[c])) + xres[o];
            }
        }
    }
}

// ------------------------- depthwise path ------------------------------------
__global__ void dw_kernel(
    const float* __restrict__ x,
    const float* __restrict__ w3,
    const float* __restrict__ b3,
    const float* __restrict__ mask,
    float* __restrict__ out)
{
    int gx = blockIdx.x * 256 + threadIdx.x;
    int gy = blockIdx.y;
    int c  = blockIdx.z;
    int p  = gy * WW + gx;
    if (mask[p] > 0.5f) return;

    const float* wc = w3 + c * 9;
    const float* xc = x + (size_t)c * HW;
    float a = 0.0f;
    #pragma unroll
    for (int k = 0; k < 9; k++) {
        int yy = reflect512(gy + (k / 3) * 2 - 2);
        int xx = reflect512(gx + (k % 3) * 2 - 2);
        a = fmaf(xc[yy * WW + xx], wc[k], a);
    }
    out[(size_t)c * HW + p] = gelu_exact(a + b3[c]) + xc[p];
}

// ------------------------- launch --------------------------------------------
extern "C" void kernel_launch(void* const* d_in, const int* in_sizes, int n_in,
                              void* d_out, int out_size) {
    const float* x    = (const float*)d_in[0];
    const float* mask = (const float*)d_in[1];
    const float* w1   = (const float*)d_in[2];
    const float* b1   = (const float*)d_in[3];
    const float* w2   = (const float*)d_in[4];
    const float* b2   = (const float*)d_in[5];
    const float* w3   = (const float*)d_in[6];
    const float* b3   = (const float*)d_in[7];
    float* out = (float*)d_out;

    static bool attr_set = false;
    if (!attr_set) {
        cudaFuncSetAttribute(conv_mma<1>,
            cudaFuncAttributeMaxDynamicSharedMemorySize, SM_TOTAL);
        cudaFuncSetAttribute(conv_mma<2>,
            cudaFuncAttributeMaxDynamicSharedMemorySize, SM_TOTAL);
        attr_set = true;
    }

    md_kernel<<<dim3(WW / 32, HH / 8), dim3(32, 8)>>>(mask);
    prep_w<<<(2 * 9 * 64 * 64 + 255) / 256, 256>>>(w1, w2);
    prep_x<<<dim3((PW + 31) / 32, PW), 256>>>(x);

    dim3 cgrid(WW / MPX, HH);   // 4 x 512

    conv_mma<1><<<cgrid, NTHR, SM_TOTAL>>>(x, b1, mask, out);
    ring_fix<<<(PW * PW + 255) / 256, 256>>>();
    conv_mma<2><<<cgrid, NTHR, SM_TOTAL>>>(x, b2, mask, out);

    dw_kernel<<<dim3(WW / 256, HH, CC), 256>>>(x, w3, b3, mask, out);
}